// round 1
// baseline (speedup 1.0000x reference)
#include <cuda_runtime.h>

#define NN 100000
#define EE 600000
#define ETOT 700000
#define DD 128
#define HH 4

// ---------------- scratch (no allocation allowed) ----------------
__device__ float d_bufA[NN * DD];
__device__ float d_bufB[NN * DD];
__device__ float d_bufH[NN * DD];
__device__ float d_el[NN * HH];
__device__ float d_er[NN * HH];
__device__ float d_sum[NN * HH];
__device__ unsigned int d_max[NN * HH];
__device__ float d_vc[2 * DD];

// order-preserving float<->uint encoding for atomicMax
__device__ __forceinline__ unsigned f_enc(float f) {
    unsigned u = __float_as_uint(f);
    return (u & 0x80000000u) ? ~u : (u | 0x80000000u);
}
__device__ __forceinline__ float f_dec(unsigned u) {
    return __uint_as_float((u & 0x80000000u) ? (u & 0x7fffffffu) : ~u);
}

// ---------------- layer 0: rank-1 collapse ----------------
// v[d] = sum_k lin_W[k] * W0[d,k] ; c[d] = sum_k lin_b[k] * W0[d,k]
__global__ void k_rank1(const float* __restrict__ lw, const float* __restrict__ lb,
                        const float* __restrict__ W0, float* __restrict__ vc) {
    int d = threadIdx.x;
    float v = 0.f, c = 0.f;
    for (int k = 0; k < DD; k++) {
        float wv = W0[d * DD + k];
        v += lw[k] * wv;
        c += lb[k] * wv;
    }
    vc[d] = v;
    vc[DD + d] = c;
}

// h0[n,d] = weights[n]*v[d] + c[d]
__global__ void k_fill0(const float* __restrict__ wts, const float* __restrict__ vc,
                        float* __restrict__ h) {
    int t = blockIdx.x * blockDim.x + threadIdx.x;
    if (t >= NN * 32) return;
    int n = t >> 5, k4 = t & 31;
    float w = wts[n];
    float4 v = *(const float4*)(vc + k4 * 4);
    float4 c = *(const float4*)(vc + DD + k4 * 4);
    float4 r = make_float4(w * v.x + c.x, w * v.y + c.y, w * v.z + c.z, w * v.w + c.w);
    *(float4*)(h + (size_t)t * 4) = r;
}

// ---------------- feature transform (layers 1,2): h = leaky(x) @ W^T ----------------
// tile: 64 nodes x 128 outputs per 256-thread block. micro-tile 4 nodes x 8 outs.
#define TPAD 132
__global__ __launch_bounds__(256, 2) void k_transform(const float* __restrict__ x,
                                                      const float* __restrict__ W,
                                                      float* __restrict__ h) {
    extern __shared__ float sm[];
    float* Ws = sm;                 // [128][TPAD]
    float* Xs = sm + DD * TPAD;     // [64][TPAD]
    int t = threadIdx.x;
    int nb = blockIdx.x * 64;
#pragma unroll
    for (int i = 0; i < 16; i++) {
        int lin = t + i * 256;      // 4096 float4
        int d = lin >> 5, k4 = lin & 31;
        float4 v = *(const float4*)(W + d * DD + k4 * 4);
        *(float4*)&Ws[d * TPAD + k4 * 4] = v;
    }
#pragma unroll
    for (int i = 0; i < 8; i++) {
        int lin = t + i * 256;      // 2048 float4 = 64 nodes * 32
        int nl = lin >> 5, k4 = lin & 31;
        int n = nb + nl;
        float4 v = make_float4(0.f, 0.f, 0.f, 0.f);
        if (n < NN) v = *(const float4*)(x + (size_t)n * DD + k4 * 4);
        v.x = v.x >= 0.f ? v.x : 0.01f * v.x;
        v.y = v.y >= 0.f ? v.y : 0.01f * v.y;
        v.z = v.z >= 0.f ? v.z : 0.01f * v.z;
        v.w = v.w >= 0.f ? v.w : 0.01f * v.w;
        *(float4*)&Xs[nl * TPAD + k4 * 4] = v;
    }
    __syncthreads();
    int tx = t & 15, ty = t >> 4;
    float acc[4][8];
#pragma unroll
    for (int i = 0; i < 4; i++)
#pragma unroll
        for (int j = 0; j < 8; j++) acc[i][j] = 0.f;
#pragma unroll 4
    for (int k = 0; k < DD; k += 4) {
        float4 xv[4];
#pragma unroll
        for (int i = 0; i < 4; i++) xv[i] = *(float4*)&Xs[(ty * 4 + i) * TPAD + k];
#pragma unroll
        for (int j = 0; j < 8; j++) {
            float4 wv = *(float4*)&Ws[(tx + 16 * j) * TPAD + k];
#pragma unroll
            for (int i = 0; i < 4; i++)
                acc[i][j] += xv[i].x * wv.x + xv[i].y * wv.y + xv[i].z * wv.z + xv[i].w * wv.w;
        }
    }
#pragma unroll
    for (int i = 0; i < 4; i++) {
        int n = nb + ty * 4 + i;
        if (n < NN) {
#pragma unroll
            for (int j = 0; j < 8; j++) h[(size_t)n * DD + tx + 16 * j] = acc[i][j];
        }
    }
}

// ---------------- el/er per node + init max/sum ----------------
__global__ void k_elar(const float* __restrict__ h, const float* __restrict__ al,
                       const float* __restrict__ ar, float* __restrict__ el,
                       float* __restrict__ er, unsigned* __restrict__ mx,
                       float* __restrict__ sm) {
    int w = (blockIdx.x * blockDim.x + threadIdx.x) >> 5;
    int lane = threadIdx.x & 31;
    if (w >= NN) return;
    float4 hv = *(const float4*)(h + (size_t)w * DD + lane * 4);
    float4 a4 = *(const float4*)(al + lane * 4);
    float4 b4 = *(const float4*)(ar + lane * 4);
    float pl = hv.x * a4.x + hv.y * a4.y + hv.z * a4.z + hv.w * a4.w;
    float pr = hv.x * b4.x + hv.y * b4.y + hv.z * b4.z + hv.w * b4.w;
    pl += __shfl_down_sync(0xffffffffu, pl, 4);
    pl += __shfl_down_sync(0xffffffffu, pl, 2);
    pl += __shfl_down_sync(0xffffffffu, pl, 1);
    pr += __shfl_down_sync(0xffffffffu, pr, 4);
    pr += __shfl_down_sync(0xffffffffu, pr, 2);
    pr += __shfl_down_sync(0xffffffffu, pr, 1);
    if ((lane & 7) == 0) {
        int hi = w * HH + (lane >> 3);
        el[hi] = pl;
        er[hi] = pr;
        mx[hi] = 0u;      // encoded -inf
        sm[hi] = 0.f;
    }
}

// ---------------- init out with conv bias ----------------
__global__ void k_initout(float* __restrict__ out, const float* __restrict__ cb) {
    int t = blockIdx.x * blockDim.x + threadIdx.x;
    if (t >= NN * 32) return;
    int k4 = t & 31;
    float4 b = *(const float4*)(cb + k4 * 4);
    *(float4*)(out + (size_t)t * 4) = b;
}

// ---------------- edge passes ----------------
__global__ void k_emax(const int* __restrict__ src, const int* __restrict__ dst,
                       const float* __restrict__ el, const float* __restrict__ er,
                       unsigned* __restrict__ mx) {
    int t = blockIdx.x * blockDim.x + threadIdx.x;
    if (t >= ETOT * HH) return;
    int e = t >> 2, h = t & 3;
    int s_ = (e < EE) ? src[e] : e - EE;
    int d_ = (e < EE) ? dst[e] : e - EE;
    float ev = el[s_ * HH + h] + er[d_ * HH + h];
    ev = ev >= 0.f ? ev : 0.2f * ev;
    atomicMax(&mx[d_ * HH + h], f_enc(ev));
}

__global__ void k_esum(const int* __restrict__ src, const int* __restrict__ dst,
                       const float* __restrict__ el, const float* __restrict__ er,
                       const unsigned* __restrict__ mx, float* __restrict__ sm) {
    int t = blockIdx.x * blockDim.x + threadIdx.x;
    if (t >= ETOT * HH) return;
    int e = t >> 2, h = t & 3;
    int s_ = (e < EE) ? src[e] : e - EE;
    int d_ = (e < EE) ? dst[e] : e - EE;
    float ev = el[s_ * HH + h] + er[d_ * HH + h];
    ev = ev >= 0.f ? ev : 0.2f * ev;
    float m = f_dec(mx[d_ * HH + h]);
    atomicAdd(&sm[d_ * HH + h], __expf(ev - m));
}

// warp per edge: out[dst, :] += h[src, :] * alpha[head]
__global__ void k_scatter(const int* __restrict__ src, const int* __restrict__ dst,
                          const float* __restrict__ el, const float* __restrict__ er,
                          const unsigned* __restrict__ mx, const float* __restrict__ sm,
                          const float* __restrict__ h, float* __restrict__ out) {
    int w = (blockIdx.x * blockDim.x + threadIdx.x) >> 5;
    int lane = threadIdx.x & 31;
    if (w >= ETOT) return;
    int s_ = (w < EE) ? src[w] : w - EE;
    int d_ = (w < EE) ? dst[w] : w - EE;
    float alpha = 0.f;
    if (lane < 4) {
        float ev = el[s_ * HH + lane] + er[d_ * HH + lane];
        ev = ev >= 0.f ? ev : 0.2f * ev;
        alpha = __expf(ev - f_dec(mx[d_ * HH + lane])) / sm[d_ * HH + lane];
    }
    float a = __shfl_sync(0xffffffffu, alpha, lane >> 3);  // head = lane/8
    float4 hv = *(const float4*)(h + (size_t)s_ * DD + lane * 4);
    float* dp = out + (size_t)d_ * DD + lane * 4;
    unsigned long long gp = (unsigned long long)__cvta_generic_to_global(dp);
    asm volatile("red.global.add.v4.f32 [%0], {%1,%2,%3,%4};" ::"l"(gp),
                 "f"(hv.x * a), "f"(hv.y * a), "f"(hv.z * a), "f"(hv.w * a)
                 : "memory");
}

// ---------------- final prediction head ----------------
__global__ void k_pred(const float* __restrict__ x, const float* __restrict__ pw,
                       const float* __restrict__ pb, float* __restrict__ out) {
    int w = (blockIdx.x * blockDim.x + threadIdx.x) >> 5;
    int lane = threadIdx.x & 31;
    if (w >= NN) return;
    float4 xv = *(const float4*)(x + (size_t)w * DD + lane * 4);
    float4 wv = *(const float4*)(pw + lane * 4);
    float p = xv.x * wv.x + xv.y * wv.y + xv.z * wv.z + xv.w * wv.w;
    p += __shfl_down_sync(0xffffffffu, p, 16);
    p += __shfl_down_sync(0xffffffffu, p, 8);
    p += __shfl_down_sync(0xffffffffu, p, 4);
    p += __shfl_down_sync(0xffffffffu, p, 2);
    p += __shfl_down_sync(0xffffffffu, p, 1);
    if (lane == 0) out[w] = p + pb[0];
}

extern "C" void kernel_launch(void* const* d_in, const int* in_sizes, int n_in,
                              void* d_out, int out_size) {
    const float* weights = (const float*)d_in[0];
    const float* lin_W   = (const float*)d_in[1];
    const float* lin_b   = (const float*)d_in[2];
    const float* fc_W    = (const float*)d_in[3];
    const float* attn_l  = (const float*)d_in[4];
    const float* attn_r  = (const float*)d_in[5];
    const float* conv_b  = (const float*)d_in[6];
    const float* pred_W  = (const float*)d_in[7];
    const float* pred_b  = (const float*)d_in[8];
    const int*   src     = (const int*)d_in[9];
    const int*   dst     = (const int*)d_in[10];

    float *bufA, *bufB, *bufH, *el, *er, *sv, *vc;
    unsigned* mv;
    cudaGetSymbolAddress((void**)&bufA, d_bufA);
    cudaGetSymbolAddress((void**)&bufB, d_bufB);
    cudaGetSymbolAddress((void**)&bufH, d_bufH);
    cudaGetSymbolAddress((void**)&el, d_el);
    cudaGetSymbolAddress((void**)&er, d_er);
    cudaGetSymbolAddress((void**)&sv, d_sum);
    cudaGetSymbolAddress((void**)&mv, d_max);
    cudaGetSymbolAddress((void**)&vc, d_vc);

    int smem = (DD * TPAD + 64 * TPAD) * 4;
    cudaFuncSetAttribute(k_transform, cudaFuncAttributeMaxDynamicSharedMemorySize, smem);

    // layer 0 transform (rank-1 collapse)
    k_rank1<<<1, DD>>>(lin_W, lin_b, fc_W, vc);
    k_fill0<<<(NN * 32 + 255) / 256, 256>>>(weights, vc, bufH);

    const float* xin = nullptr;
    float* xout = bufA;
    for (int l = 0; l < 3; l++) {
        if (l > 0)
            k_transform<<<(NN + 63) / 64, 256, smem>>>(xin, fc_W + l * DD * DD, bufH);
        k_elar<<<(NN + 7) / 8, 256>>>(bufH, attn_l + l * HH * 32, attn_r + l * HH * 32,
                                      el, er, mv, sv);
        k_initout<<<(NN * 32 + 255) / 256, 256>>>(xout, conv_b + l * DD);
        k_emax<<<(ETOT * HH + 255) / 256, 256>>>(src, dst, el, er, mv);
        k_esum<<<(ETOT * HH + 255) / 256, 256>>>(src, dst, el, er, mv, sv);
        k_scatter<<<(ETOT + 7) / 8, 256>>>(src, dst, el, er, mv, sv, bufH, xout);
        xin = xout;
        xout = (l == 0) ? bufB : bufA;
    }
    k_pred<<<(NN + 7) / 8, 256>>>(xin, pred_W, pred_b, (float*)d_out);
}

// round 3
// speedup vs baseline: 1.1015x; 1.1015x over previous
#include <cuda_runtime.h>
#include <math_constants.h>

#define NN 100000
#define EE 600000
#define ETOT 700000
#define DD 128
#define HH 4

// ---------------- scratch (no allocation allowed) ----------------
__device__ float d_bufA[NN * DD];
__device__ float d_bufB[NN * DD];
__device__ float d_bufH[NN * DD];
__device__ float d_el[NN * HH];
__device__ float d_er[NN * HH];
__device__ float d_vc[2 * DD];
__device__ int d_deg[NN];
__device__ int d_fill[NN];
__device__ int d_rowptr[NN + 1];
__device__ int d_col[ETOT];

// ---------------- layer 0: rank-1 collapse ----------------
__global__ void k_rank1(const float* __restrict__ lw, const float* __restrict__ lb,
                        const float* __restrict__ W0, float* __restrict__ vc) {
    int d = threadIdx.x;
    float v = 0.f, c = 0.f;
    for (int k = 0; k < DD; k++) {
        float wv = W0[d * DD + k];
        v += lw[k] * wv;
        c += lb[k] * wv;
    }
    vc[d] = v;
    vc[DD + d] = c;
}

__global__ void k_fill0(const float* __restrict__ wts, const float* __restrict__ vc,
                        float* __restrict__ h) {
    int t = blockIdx.x * blockDim.x + threadIdx.x;
    if (t >= NN * 32) return;
    int n = t >> 5, k4 = t & 31;
    float w = wts[n];
    float4 v = *(const float4*)(vc + k4 * 4);
    float4 c = *(const float4*)(vc + DD + k4 * 4);
    float4 r = make_float4(w * v.x + c.x, w * v.y + c.y, w * v.z + c.z, w * v.w + c.w);
    *(float4*)(h + (size_t)t * 4) = r;
}

// ---------------- CSR build (once per call, reused by all 3 layers) ----------
__global__ void k_deg_init(int* __restrict__ deg, int* __restrict__ fill) {
    int t = blockIdx.x * blockDim.x + threadIdx.x;
    if (t < NN) { deg[t] = 1; fill[t] = 0; }   // 1 = self loop
}

__global__ void k_deg(const int* __restrict__ dst, int* __restrict__ deg) {
    int t = blockIdx.x * blockDim.x + threadIdx.x;
    if (t < EE) atomicAdd(&deg[dst[t]], 1);
}

// single-block exclusive scan over deg[NN] -> rowptr[NN+1]
__global__ void k_scan(const int* __restrict__ deg, int* __restrict__ rowptr) {
    __shared__ int part[1024];
    int t = threadIdx.x;
    const int CH = (NN + 1023) / 1024;   // 98
    int start = t * CH;
    int end = start + CH; if (end > NN) end = NN;
    int s = 0;
    for (int i = start; i < end; i++) s += deg[i];
    part[t] = s;
    __syncthreads();
    for (int off = 1; off < 1024; off <<= 1) {
        int v = (t >= off) ? part[t - off] : 0;
        __syncthreads();
        part[t] += v;
        __syncthreads();
    }
    int base = (t == 0) ? 0 : part[t - 1];
    for (int i = start; i < end; i++) { rowptr[i] = base; base += deg[i]; }
    if (t == 1023) rowptr[NN] = part[1023];
}

__global__ void k_csr_fill(const int* __restrict__ src, const int* __restrict__ dst,
                           const int* __restrict__ rowptr, int* __restrict__ fill,
                           int* __restrict__ col) {
    int e = blockIdx.x * blockDim.x + threadIdx.x;
    if (e >= ETOT) return;
    int s_ = (e < EE) ? src[e] : e - EE;
    int d_ = (e < EE) ? dst[e] : e - EE;
    int pos = rowptr[d_] + atomicAdd(&fill[d_], 1);
    col[pos] = s_;
}

// ---------------- feature transform (layers 1,2): h = leaky(x) @ W^T ----------
#define TPAD 132
__global__ __launch_bounds__(256, 2) void k_transform(const float* __restrict__ x,
                                                      const float* __restrict__ W,
                                                      float* __restrict__ h) {
    extern __shared__ float sm[];
    float* Ws = sm;                 // [128][TPAD]
    float* Xs = sm + DD * TPAD;     // [64][TPAD]
    int t = threadIdx.x;
    int nb = blockIdx.x * 64;
#pragma unroll
    for (int i = 0; i < 16; i++) {
        int lin = t + i * 256;
        int d = lin >> 5, k4 = lin & 31;
        float4 v = *(const float4*)(W + d * DD + k4 * 4);
        *(float4*)&Ws[d * TPAD + k4 * 4] = v;
    }
#pragma unroll
    for (int i = 0; i < 8; i++) {
        int lin = t + i * 256;
        int nl = lin >> 5, k4 = lin & 31;
        int n = nb + nl;
        float4 v = make_float4(0.f, 0.f, 0.f, 0.f);
        if (n < NN) v = *(const float4*)(x + (size_t)n * DD + k4 * 4);
        v.x = v.x >= 0.f ? v.x : 0.01f * v.x;
        v.y = v.y >= 0.f ? v.y : 0.01f * v.y;
        v.z = v.z >= 0.f ? v.z : 0.01f * v.z;
        v.w = v.w >= 0.f ? v.w : 0.01f * v.w;
        *(float4*)&Xs[nl * TPAD + k4 * 4] = v;
    }
    __syncthreads();
    int tx = t & 15, ty = t >> 4;
    float acc[4][8];
#pragma unroll
    for (int i = 0; i < 4; i++)
#pragma unroll
        for (int j = 0; j < 8; j++) acc[i][j] = 0.f;
#pragma unroll 4
    for (int k = 0; k < DD; k += 4) {
        float4 xv[4];
#pragma unroll
        for (int i = 0; i < 4; i++) xv[i] = *(float4*)&Xs[(ty * 4 + i) * TPAD + k];
#pragma unroll
        for (int j = 0; j < 8; j++) {
            float4 wv = *(float4*)&Ws[(tx + 16 * j) * TPAD + k];
#pragma unroll
            for (int i = 0; i < 4; i++)
                acc[i][j] += xv[i].x * wv.x + xv[i].y * wv.y + xv[i].z * wv.z + xv[i].w * wv.w;
        }
    }
#pragma unroll
    for (int i = 0; i < 4; i++) {
        int n = nb + ty * 4 + i;
        if (n < NN) {
#pragma unroll
            for (int j = 0; j < 8; j++) h[(size_t)n * DD + tx + 16 * j] = acc[i][j];
        }
    }
}

// ---------------- el/er per node ----------------
__global__ void k_elar(const float* __restrict__ h, const float* __restrict__ al,
                       const float* __restrict__ ar, float* __restrict__ el,
                       float* __restrict__ er) {
    int w = (blockIdx.x * blockDim.x + threadIdx.x) >> 5;
    int lane = threadIdx.x & 31;
    if (w >= NN) return;
    float4 hv = *(const float4*)(h + (size_t)w * DD + lane * 4);
    float4 a4 = *(const float4*)(al + lane * 4);
    float4 b4 = *(const float4*)(ar + lane * 4);
    float pl = hv.x * a4.x + hv.y * a4.y + hv.z * a4.z + hv.w * a4.w;
    float pr = hv.x * b4.x + hv.y * b4.y + hv.z * b4.z + hv.w * b4.w;
    pl += __shfl_down_sync(0xffffffffu, pl, 4);
    pl += __shfl_down_sync(0xffffffffu, pl, 2);
    pl += __shfl_down_sync(0xffffffffu, pl, 1);
    pr += __shfl_down_sync(0xffffffffu, pr, 4);
    pr += __shfl_down_sync(0xffffffffu, pr, 2);
    pr += __shfl_down_sync(0xffffffffu, pr, 1);
    if ((lane & 7) == 0) {
        int hi = w * HH + (lane >> 3);
        el[hi] = pl;
        er[hi] = pr;
    }
}

// ---------------- fused per-node softmax aggregation (warp per node) --------
__device__ __forceinline__ float4 leaky4(float4 v) {
    v.x = v.x >= 0.f ? v.x : 0.2f * v.x;
    v.y = v.y >= 0.f ? v.y : 0.2f * v.y;
    v.z = v.z >= 0.f ? v.z : 0.2f * v.z;
    v.w = v.w >= 0.f ? v.w : 0.2f * v.w;
    return v;
}

__global__ __launch_bounds__(256) void k_agg(const int* __restrict__ rowptr,
                                             const int* __restrict__ col,
                                             const float* __restrict__ el,
                                             const float* __restrict__ er,
                                             const float* __restrict__ h,
                                             const float* __restrict__ cb,
                                             float* __restrict__ out) {
    int w = (blockIdx.x * blockDim.x + threadIdx.x) >> 5;
    int lane = threadIdx.x & 31;
    if (w >= NN) return;
    int beg = rowptr[w], end = rowptr[w + 1];
    float4 erd = *(const float4*)(er + w * HH);

    // pass 1: per-head max (all lanes redundantly)
    float4 m = make_float4(-CUDART_INF_F, -CUDART_INF_F, -CUDART_INF_F, -CUDART_INF_F);
    for (int i = beg; i < end; i++) {
        int s_ = __ldg(&col[i]);
        float4 e4 = *(const float4*)(el + s_ * HH);
        e4 = leaky4(make_float4(e4.x + erd.x, e4.y + erd.y, e4.z + erd.z, e4.w + erd.w));
        m.x = fmaxf(m.x, e4.x); m.y = fmaxf(m.y, e4.y);
        m.z = fmaxf(m.z, e4.z); m.w = fmaxf(m.w, e4.w);
    }

    // pass 2: unnormalized accumulate; lane owns features [lane*4, lane*4+4)
    int head = lane >> 3;
    float4 sum = make_float4(0.f, 0.f, 0.f, 0.f);
    float4 acc = make_float4(0.f, 0.f, 0.f, 0.f);
    for (int i = beg; i < end; i++) {
        int s_ = __ldg(&col[i]);
        float4 e4 = *(const float4*)(el + s_ * HH);
        e4 = leaky4(make_float4(e4.x + erd.x, e4.y + erd.y, e4.z + erd.z, e4.w + erd.w));
        float4 wv = make_float4(__expf(e4.x - m.x), __expf(e4.y - m.y),
                                __expf(e4.z - m.z), __expf(e4.w - m.w));
        sum.x += wv.x; sum.y += wv.y; sum.z += wv.z; sum.w += wv.w;
        float a = (head == 0) ? wv.x : (head == 1) ? wv.y : (head == 2) ? wv.z : wv.w;
        float4 hv = *(const float4*)(h + (size_t)s_ * DD + lane * 4);
        acc.x += hv.x * a; acc.y += hv.y * a; acc.z += hv.z * a; acc.w += hv.w * a;
    }
    float sden = (head == 0) ? sum.x : (head == 1) ? sum.y : (head == 2) ? sum.z : sum.w;
    float inv = 1.f / sden;
    float4 b = *(const float4*)(cb + lane * 4);
    float4 r = make_float4(acc.x * inv + b.x, acc.y * inv + b.y,
                           acc.z * inv + b.z, acc.w * inv + b.w);
    *(float4*)(out + (size_t)w * DD + lane * 4) = r;
}

// ---------------- final prediction head ----------------
__global__ void k_pred(const float* __restrict__ x, const float* __restrict__ pw,
                       const float* __restrict__ pb, float* __restrict__ out) {
    int w = (blockIdx.x * blockDim.x + threadIdx.x) >> 5;
    int lane = threadIdx.x & 31;
    if (w >= NN) return;
    float4 xv = *(const float4*)(x + (size_t)w * DD + lane * 4);
    float4 wv = *(const float4*)(pw + lane * 4);
    float p = xv.x * wv.x + xv.y * wv.y + xv.z * wv.z + xv.w * wv.w;
    p += __shfl_down_sync(0xffffffffu, p, 16);
    p += __shfl_down_sync(0xffffffffu, p, 8);
    p += __shfl_down_sync(0xffffffffu, p, 4);
    p += __shfl_down_sync(0xffffffffu, p, 2);
    p += __shfl_down_sync(0xffffffffu, p, 1);
    if (lane == 0) out[w] = p + pb[0];
}

extern "C" void kernel_launch(void* const* d_in, const int* in_sizes, int n_in,
                              void* d_out, int out_size) {
    const float* weights = (const float*)d_in[0];
    const float* lin_W   = (const float*)d_in[1];
    const float* lin_b   = (const float*)d_in[2];
    const float* fc_W    = (const float*)d_in[3];
    const float* attn_l  = (const float*)d_in[4];
    const float* attn_r  = (const float*)d_in[5];
    const float* conv_b  = (const float*)d_in[6];
    const float* pred_W  = (const float*)d_in[7];
    const float* pred_b  = (const float*)d_in[8];
    const int*   src     = (const int*)d_in[9];
    const int*   dst     = (const int*)d_in[10];

    float *bufA, *bufB, *bufH, *el, *er, *vc;
    int *deg, *fill, *rowptr, *colp;
    cudaGetSymbolAddress((void**)&bufA, d_bufA);
    cudaGetSymbolAddress((void**)&bufB, d_bufB);
    cudaGetSymbolAddress((void**)&bufH, d_bufH);
    cudaGetSymbolAddress((void**)&el, d_el);
    cudaGetSymbolAddress((void**)&er, d_er);
    cudaGetSymbolAddress((void**)&vc, d_vc);
    cudaGetSymbolAddress((void**)&deg, d_deg);
    cudaGetSymbolAddress((void**)&fill, d_fill);
    cudaGetSymbolAddress((void**)&rowptr, d_rowptr);
    cudaGetSymbolAddress((void**)&colp, d_col);

    int smem = (DD * TPAD + 64 * TPAD) * 4;
    cudaFuncSetAttribute(k_transform, cudaFuncAttributeMaxDynamicSharedMemorySize, smem);

    // CSR build (once; the graph is the same for all 3 layers)
    k_deg_init<<<(NN + 255) / 256, 256>>>(deg, fill);
    k_deg<<<(EE + 255) / 256, 256>>>(dst, deg);
    k_scan<<<1, 1024>>>(deg, rowptr);
    k_csr_fill<<<(ETOT + 255) / 256, 256>>>(src, dst, rowptr, fill, colp);

    // layer 0 transform (rank-1 collapse)
    k_rank1<<<1, DD>>>(lin_W, lin_b, fc_W, vc);
    k_fill0<<<(NN * 32 + 255) / 256, 256>>>(weights, vc, bufH);

    const float* xin = nullptr;
    float* xout = bufA;
    for (int l = 0; l < 3; l++) {
        if (l > 0)
            k_transform<<<(NN + 63) / 64, 256, smem>>>(xin, fc_W + l * DD * DD, bufH);
        k_elar<<<(NN + 7) / 8, 256>>>(bufH, attn_l + l * HH * 32, attn_r + l * HH * 32,
                                      el, er);
        k_agg<<<(NN + 7) / 8, 256>>>(rowptr, colp, el, er, bufH, conv_b + l * DD, xout);
        xin = xout;
        xout = (l == 0) ? bufB : bufA;
    }
    k_pred<<<(NN + 7) / 8, 256>>>(xin, pred_W, pred_b, (float*)d_out);
}

// round 5
// speedup vs baseline: 1.1862x; 1.0769x over previous
#include <cuda_runtime.h>
#include <cuda_bf16.h>
#include <math_constants.h>
#include <cstdint>

#define NN 100000
#define EE 600000
#define ETOT 700000
#define DD 128
#define HH 4

// ---------------- scratch (no allocation allowed) ----------------
__device__ float d_bufA[NN * DD];
__device__ float d_bufB[NN * DD];
__device__ float d_bufH[NN * DD];
__device__ float d_el[NN * HH];
__device__ float d_er[NN * HH];
__device__ float d_vc[2 * DD];
__device__ int d_deg[NN];
__device__ int d_fill[NN];
__device__ int d_rowptr[NN + 1];
__device__ int d_col[ETOT];
__device__ __nv_bfloat16 d_whi[3 * DD * DD];
__device__ __nv_bfloat16 d_wlo[3 * DD * DD];

// ---------------- layer 0: rank-1 collapse ----------------
__global__ void k_rank1(const float* __restrict__ lw, const float* __restrict__ lb,
                        const float* __restrict__ W0, float* __restrict__ vc) {
    int d = threadIdx.x;
    float v = 0.f, c = 0.f;
    for (int k = 0; k < DD; k++) {
        float wv = W0[d * DD + k];
        v += lw[k] * wv;
        c += lb[k] * wv;
    }
    vc[d] = v;
    vc[DD + d] = c;
}

__global__ void k_fill0(const float* __restrict__ wts, const float* __restrict__ vc,
                        float* __restrict__ h) {
    int t = blockIdx.x * blockDim.x + threadIdx.x;
    if (t >= NN * 32) return;
    int n = t >> 5, k4 = t & 31;
    float w = wts[n];
    float4 v = *(const float4*)(vc + k4 * 4);
    float4 c = *(const float4*)(vc + DD + k4 * 4);
    float4 r = make_float4(w * v.x + c.x, w * v.y + c.y, w * v.z + c.z, w * v.w + c.w);
    *(float4*)(h + (size_t)t * 4) = r;
}

// ---------------- W split (plain row-major bf16 hi/lo) ----------------------
__global__ void k_wsplit(const float* __restrict__ fcW, __nv_bfloat16* __restrict__ whi,
                         __nv_bfloat16* __restrict__ wlo) {
    int t = blockIdx.x * blockDim.x + threadIdx.x;
    if (t >= 3 * DD * DD) return;
    float w = fcW[t];
    __nv_bfloat16 hi = __float2bfloat16(w);
    __nv_bfloat16 lo = __float2bfloat16(w - __bfloat162float(hi));
    whi[t] = hi;
    wlo[t] = lo;
}

// ---------------- CSR build ----------------
__global__ void k_deg_init(int* __restrict__ deg, int* __restrict__ fill) {
    int t = blockIdx.x * blockDim.x + threadIdx.x;
    if (t < NN) { deg[t] = 1; fill[t] = 0; }
}

__global__ void k_deg(const int* __restrict__ dst, int* __restrict__ deg) {
    int t = blockIdx.x * blockDim.x + threadIdx.x;
    if (t < EE) atomicAdd(&deg[dst[t]], 1);
}

__global__ void k_scan(const int* __restrict__ deg, int* __restrict__ rowptr) {
    __shared__ int part[1024];
    int t = threadIdx.x;
    const int CH = (NN + 1023) / 1024;
    int start = t * CH;
    int end = start + CH; if (end > NN) end = NN;
    int s = 0;
    for (int i = start; i < end; i++) s += deg[i];
    part[t] = s;
    __syncthreads();
    for (int off = 1; off < 1024; off <<= 1) {
        int v = (t >= off) ? part[t - off] : 0;
        __syncthreads();
        part[t] += v;
        __syncthreads();
    }
    int base = (t == 0) ? 0 : part[t - 1];
    for (int i = start; i < end; i++) { rowptr[i] = base; base += deg[i]; }
    if (t == 1023) rowptr[NN] = part[1023];
}

__global__ void k_csr_fill(const int* __restrict__ src, const int* __restrict__ dst,
                           const int* __restrict__ rowptr, int* __restrict__ fill,
                           int* __restrict__ col) {
    int e = blockIdx.x * blockDim.x + threadIdx.x;
    if (e >= ETOT) return;
    int s_ = (e < EE) ? src[e] : e - EE;
    int d_ = (e < EE) ? dst[e] : e - EE;
    int pos = rowptr[d_] + atomicAdd(&fill[d_], 1);
    col[pos] = s_;
}

// ---------------- tensor-core transform via mma.sync bf16 -------------------
// h = leaky(x) @ W^T.  Split: D = xh*Wh + xh*Wl + xl*Wh (fp32 accum).
// CTA: 128 nodes x 128 outs, 8 warps (4M x 2N), warp tile 32x64.
#define XPITCH 136
#define SM_XH 0
#define SM_XL (128 * XPITCH)
#define SM_WH (2 * 128 * XPITCH)
#define SM_WL (3 * 128 * XPITCH)
#define SMEM_MMA (4 * 128 * XPITCH * 2)

__device__ __forceinline__ void mma16816(float* c, const uint32_t* a, const uint32_t* b) {
    asm volatile(
        "mma.sync.aligned.m16n8k16.row.col.f32.bf16.bf16.f32 "
        "{%0,%1,%2,%3}, {%4,%5,%6,%7}, {%8,%9}, {%0,%1,%2,%3};"
        : "+f"(c[0]), "+f"(c[1]), "+f"(c[2]), "+f"(c[3])
        : "r"(a[0]), "r"(a[1]), "r"(a[2]), "r"(a[3]), "r"(b[0]), "r"(b[1]));
}

__global__ __launch_bounds__(256, 1) void k_transform_mma(const float* __restrict__ x,
                                                          const __nv_bfloat16* __restrict__ Whi,
                                                          const __nv_bfloat16* __restrict__ Wlo,
                                                          float* __restrict__ h) {
    extern __shared__ __nv_bfloat16 sm[];
    __nv_bfloat16* sXh = sm + SM_XH;
    __nv_bfloat16* sXl = sm + SM_XL;
    __nv_bfloat16* sWh = sm + SM_WH;
    __nv_bfloat16* sWl = sm + SM_WL;
    int tid = threadIdx.x;
    int nb = blockIdx.x * 128;

    // load W hi/lo (row-major [128][128] -> padded [128][136])
    {
        const uint4* wh4 = (const uint4*)Whi;
        const uint4* wl4 = (const uint4*)Wlo;
#pragma unroll
        for (int i = 0; i < 8; i++) {
            int idx = tid + i * 256;          // 2048 uint4 = 16384 bf16
            int r = idx >> 4, c = idx & 15;
            *(uint4*)&sWh[r * XPITCH + c * 8] = wh4[idx];
            *(uint4*)&sWl[r * XPITCH + c * 8] = wl4[idx];
        }
    }

    // load x: 2 threads per row, leaky + split hi/lo
    {
        int row = tid >> 1, half = tid & 1;
        int n = nb + row;
        int kb = half * 64;
        if (n < NN) {
            const float4* xr = (const float4*)(x + (size_t)n * DD) + half * 16;
#pragma unroll
            for (int i = 0; i < 16; i++) {
                float4 v = xr[i];
                float f[4] = {v.x, v.y, v.z, v.w};
                uint32_t hw[2], lw[2];
#pragma unroll
                for (int j = 0; j < 4; j += 2) {
                    float a = f[j] >= 0.f ? f[j] : 0.01f * f[j];
                    float b = f[j + 1] >= 0.f ? f[j + 1] : 0.01f * f[j + 1];
                    __nv_bfloat16 ah = __float2bfloat16(a);
                    __nv_bfloat16 bh = __float2bfloat16(b);
                    __nv_bfloat16 al = __float2bfloat16(a - __bfloat162float(ah));
                    __nv_bfloat16 bl = __float2bfloat16(b - __bfloat162float(bh));
                    hw[j >> 1] = (uint32_t)__bfloat16_as_ushort(ah) |
                                 ((uint32_t)__bfloat16_as_ushort(bh) << 16);
                    lw[j >> 1] = (uint32_t)__bfloat16_as_ushort(al) |
                                 ((uint32_t)__bfloat16_as_ushort(bl) << 16);
                }
                *(uint2*)&sXh[row * XPITCH + kb + i * 4] = make_uint2(hw[0], hw[1]);
                *(uint2*)&sXl[row * XPITCH + kb + i * 4] = make_uint2(lw[0], lw[1]);
            }
        } else {
            uint2 z = make_uint2(0u, 0u);
#pragma unroll
            for (int i = 0; i < 16; i++) {
                *(uint2*)&sXh[row * XPITCH + kb + i * 4] = z;
                *(uint2*)&sXl[row * XPITCH + kb + i * 4] = z;
            }
        }
    }
    __syncthreads();

    int wid = tid >> 5, lane = tid & 31;
    int g = lane >> 2, tig = lane & 3;
    int mbase = (wid >> 1) * 32;
    int nbase = (wid & 1) * 64;

    float acc[2][8][4];
#pragma unroll
    for (int mt = 0; mt < 2; mt++)
#pragma unroll
        for (int nt = 0; nt < 8; nt++)
#pragma unroll
            for (int c = 0; c < 4; c++) acc[mt][nt][c] = 0.f;

    const __nv_bfloat16* Ab[3] = {sXh, sXh, sXl};
    const __nv_bfloat16* Bb[3] = {sWh, sWl, sWh};
#pragma unroll
    for (int p = 0; p < 3; p++) {
        const __nv_bfloat16* A = Ab[p];
        const __nv_bfloat16* B = Bb[p];
#pragma unroll
        for (int ks = 0; ks < 8; ks++) {
            int k0 = ks * 16 + tig * 2;
            uint32_t a[2][4], b[8][2];
#pragma unroll
            for (int mt = 0; mt < 2; mt++) {
                int r = mbase + mt * 16 + g;
                a[mt][0] = *(const uint32_t*)&A[r * XPITCH + k0];
                a[mt][1] = *(const uint32_t*)&A[(r + 8) * XPITCH + k0];
                a[mt][2] = *(const uint32_t*)&A[r * XPITCH + k0 + 8];
                a[mt][3] = *(const uint32_t*)&A[(r + 8) * XPITCH + k0 + 8];
            }
#pragma unroll
            for (int nt = 0; nt < 8; nt++) {
                int n = nbase + nt * 8 + g;
                b[nt][0] = *(const uint32_t*)&B[n * XPITCH + k0];
                b[nt][1] = *(const uint32_t*)&B[n * XPITCH + k0 + 8];
            }
#pragma unroll
            for (int mt = 0; mt < 2; mt++)
#pragma unroll
                for (int nt = 0; nt < 8; nt++) mma16816(acc[mt][nt], a[mt], b[nt]);
        }
    }

    // stage C through smem (reuse sXh/sXl region: 128*132 floats = 67.6KB <= 69.6KB)
    __syncthreads();
    float* stg = (float*)sm;
#pragma unroll
    for (int mt = 0; mt < 2; mt++) {
        int r = mbase + mt * 16 + g;
#pragma unroll
        for (int nt = 0; nt < 8; nt++) {
            int c0 = nbase + nt * 8 + tig * 2;
            stg[r * 132 + c0] = acc[mt][nt][0];
            stg[r * 132 + c0 + 1] = acc[mt][nt][1];
            stg[(r + 8) * 132 + c0] = acc[mt][nt][2];
            stg[(r + 8) * 132 + c0 + 1] = acc[mt][nt][3];
        }
    }
    __syncthreads();

    int col = tid & 127;
#pragma unroll
    for (int r = tid >> 7; r < 128; r += 2) {
        int n2 = nb + r;
        if (n2 < NN) h[(size_t)n2 * DD + col] = stg[r * 132 + col];
    }
}

// ---------------- el/er per node ----------------
__global__ void k_elar(const float* __restrict__ h, const float* __restrict__ al,
                       const float* __restrict__ ar, float* __restrict__ el,
                       float* __restrict__ er) {
    int w = (blockIdx.x * blockDim.x + threadIdx.x) >> 5;
    int lane = threadIdx.x & 31;
    if (w >= NN) return;
    float4 hv = *(const float4*)(h + (size_t)w * DD + lane * 4);
    float4 a4 = *(const float4*)(al + lane * 4);
    float4 b4 = *(const float4*)(ar + lane * 4);
    float pl = hv.x * a4.x + hv.y * a4.y + hv.z * a4.z + hv.w * a4.w;
    float pr = hv.x * b4.x + hv.y * b4.y + hv.z * b4.z + hv.w * b4.w;
    pl += __shfl_down_sync(0xffffffffu, pl, 4);
    pl += __shfl_down_sync(0xffffffffu, pl, 2);
    pl += __shfl_down_sync(0xffffffffu, pl, 1);
    pr += __shfl_down_sync(0xffffffffu, pr, 4);
    pr += __shfl_down_sync(0xffffffffu, pr, 2);
    pr += __shfl_down_sync(0xffffffffu, pr, 1);
    if ((lane & 7) == 0) {
        int hi = w * HH + (lane >> 3);
        el[hi] = pl;
        er[hi] = pr;
    }
}

// ---------------- fused per-node softmax aggregation (warp per node) --------
__device__ __forceinline__ float4 leaky4(float4 v) {
    v.x = v.x >= 0.f ? v.x : 0.2f * v.x;
    v.y = v.y >= 0.f ? v.y : 0.2f * v.y;
    v.z = v.z >= 0.f ? v.z : 0.2f * v.z;
    v.w = v.w >= 0.f ? v.w : 0.2f * v.w;
    return v;
}

__global__ __launch_bounds__(256) void k_agg(const int* __restrict__ rowptr,
                                             const int* __restrict__ col,
                                             const float* __restrict__ el,
                                             const float* __restrict__ er,
                                             const float* __restrict__ h,
                                             const float* __restrict__ cb,
                                             float* __restrict__ out) {
    int w = (blockIdx.x * blockDim.x + threadIdx.x) >> 5;
    int lane = threadIdx.x & 31;
    if (w >= NN) return;
    int beg = rowptr[w], end = rowptr[w + 1];
    float4 erd = *(const float4*)(er + w * HH);

    float4 m = make_float4(-CUDART_INF_F, -CUDART_INF_F, -CUDART_INF_F, -CUDART_INF_F);
    for (int i = beg; i < end; i++) {
        int s_ = __ldg(&col[i]);
        float4 e4 = *(const float4*)(el + s_ * HH);
        e4 = leaky4(make_float4(e4.x + erd.x, e4.y + erd.y, e4.z + erd.z, e4.w + erd.w));
        m.x = fmaxf(m.x, e4.x); m.y = fmaxf(m.y, e4.y);
        m.z = fmaxf(m.z, e4.z); m.w = fmaxf(m.w, e4.w);
    }

    int head = lane >> 3;
    float4 sum = make_float4(0.f, 0.f, 0.f, 0.f);
    float4 acc = make_float4(0.f, 0.f, 0.f, 0.f);
    for (int i = beg; i < end; i++) {
        int s_ = __ldg(&col[i]);
        float4 e4 = *(const float4*)(el + s_ * HH);
        e4 = leaky4(make_float4(e4.x + erd.x, e4.y + erd.y, e4.z + erd.z, e4.w + erd.w));
        float4 wv = make_float4(__expf(e4.x - m.x), __expf(e4.y - m.y),
                                __expf(e4.z - m.z), __expf(e4.w - m.w));
        sum.x += wv.x; sum.y += wv.y; sum.z += wv.z; sum.w += wv.w;
        float a = (head == 0) ? wv.x : (head == 1) ? wv.y : (head == 2) ? wv.z : wv.w;
        float4 hv = *(const float4*)(h + (size_t)s_ * DD + lane * 4);
        acc.x += hv.x * a; acc.y += hv.y * a; acc.z += hv.z * a; acc.w += hv.w * a;
    }
    float sden = (head == 0) ? sum.x : (head == 1) ? sum.y : (head == 2) ? sum.z : sum.w;
    float inv = 1.f / sden;
    float4 b = *(const float4*)(cb + lane * 4);
    float4 r = make_float4(acc.x * inv + b.x, acc.y * inv + b.y,
                           acc.z * inv + b.z, acc.w * inv + b.w);
    *(float4*)(out + (size_t)w * DD + lane * 4) = r;
}

// ---------------- final prediction head ----------------
__global__ void k_pred(const float* __restrict__ x, const float* __restrict__ pw,
                       const float* __restrict__ pb, float* __restrict__ out) {
    int w = (blockIdx.x * blockDim.x + threadIdx.x) >> 5;
    int lane = threadIdx.x & 31;
    if (w >= NN) return;
    float4 xv = *(const float4*)(x + (size_t)w * DD + lane * 4);
    float4 wv = *(const float4*)(pw + lane * 4);
    float p = xv.x * wv.x + xv.y * wv.y + xv.z * wv.z + xv.w * wv.w;
    p += __shfl_down_sync(0xffffffffu, p, 16);
    p += __shfl_down_sync(0xffffffffu, p, 8);
    p += __shfl_down_sync(0xffffffffu, p, 4);
    p += __shfl_down_sync(0xffffffffu, p, 2);
    p += __shfl_down_sync(0xffffffffu, p, 1);
    if (lane == 0) out[w] = p + pb[0];
}

extern "C" void kernel_launch(void* const* d_in, const int* in_sizes, int n_in,
                              void* d_out, int out_size) {
    const float* weights = (const float*)d_in[0];
    const float* lin_W   = (const float*)d_in[1];
    const float* lin_b   = (const float*)d_in[2];
    const float* fc_W    = (const float*)d_in[3];
    const float* attn_l  = (const float*)d_in[4];
    const float* attn_r  = (const float*)d_in[5];
    const float* conv_b  = (const float*)d_in[6];
    const float* pred_W  = (const float*)d_in[7];
    const float* pred_b  = (const float*)d_in[8];
    const int*   src     = (const int*)d_in[9];
    const int*   dst     = (const int*)d_in[10];

    float *bufA, *bufB, *bufH, *el, *er, *vc;
    int *deg, *fill, *rowptr, *colp;
    __nv_bfloat16 *whi, *wlo;
    cudaGetSymbolAddress((void**)&bufA, d_bufA);
    cudaGetSymbolAddress((void**)&bufB, d_bufB);
    cudaGetSymbolAddress((void**)&bufH, d_bufH);
    cudaGetSymbolAddress((void**)&el, d_el);
    cudaGetSymbolAddress((void**)&er, d_er);
    cudaGetSymbolAddress((void**)&vc, d_vc);
    cudaGetSymbolAddress((void**)&deg, d_deg);
    cudaGetSymbolAddress((void**)&fill, d_fill);
    cudaGetSymbolAddress((void**)&rowptr, d_rowptr);
    cudaGetSymbolAddress((void**)&colp, d_col);
    cudaGetSymbolAddress((void**)&whi, d_whi);
    cudaGetSymbolAddress((void**)&wlo, d_wlo);

    cudaFuncSetAttribute(k_transform_mma, cudaFuncAttributeMaxDynamicSharedMemorySize,
                         SMEM_MMA);

    // CSR build (graph identical for all 3 layers)
    k_deg_init<<<(NN + 255) / 256, 256>>>(deg, fill);
    k_deg<<<(EE + 255) / 256, 256>>>(dst, deg);
    k_scan<<<1, 1024>>>(deg, rowptr);
    k_csr_fill<<<(ETOT + 255) / 256, 256>>>(src, dst, rowptr, fill, colp);

    // W split for layers 1,2 (layer 0 uses rank-1 collapse)
    k_wsplit<<<(3 * DD * DD + 255) / 256, 256>>>(fc_W, whi, wlo);

    // layer 0 transform
    k_rank1<<<1, DD>>>(lin_W, lin_b, fc_W, vc);
    k_fill0<<<(NN * 32 + 255) / 256, 256>>>(weights, vc, bufH);

    const float* xin = nullptr;
    float* xout = bufA;
    for (int l = 0; l < 3; l++) {
        if (l > 0)
            k_transform_mma<<<(NN + 127) / 128, 256, SMEM_MMA>>>(
                xin, whi + l * DD * DD, wlo + l * DD * DD, bufH);
        k_elar<<<(NN + 7) / 8, 256>>>(bufH, attn_l + l * HH * 32, attn_r + l * HH * 32,
                                      el, er);
        k_agg<<<(NN + 7) / 8, 256>>>(rowptr, colp, el, er, bufH, conv_b + l * DD, xout);
        xin = xout;
        xout = (l == 0) ? bufB : bufA;
    }
    k_pred<<<(NN + 7) / 8, 256>>>(xin, pred_W, pred_b, (float*)d_out);
}

// round 7
// speedup vs baseline: 1.3834x; 1.1662x over previous
#include <cuda_runtime.h>
#include <cuda_bf16.h>
#include <math_constants.h>
#include <cstdint>

#define NN 100000
#define EE 600000
#define ETOT 700000
#define DD 128
#define HH 4

// ---------------- scratch (no allocation allowed) ----------------
__device__ float d_bufA[NN * DD];
__device__ float d_bufB[NN * DD];
__device__ float d_bufH[NN * DD];
__device__ float d_el[NN * HH];
__device__ float d_er[NN * HH];
__device__ float d_vc[2 * DD];
__device__ int d_deg[NN];
__device__ int d_fill[NN];
__device__ int d_rowptr[NN + 1];
__device__ int d_col[ETOT];
__device__ __nv_bfloat16 d_whi[3 * DD * DD];
__device__ __nv_bfloat16 d_wlo[3 * DD * DD];

// ---------------- layer 0: rank-1 collapse ----------------
__global__ void k_rank1(const float* __restrict__ lw, const float* __restrict__ lb,
                        const float* __restrict__ W0, float* __restrict__ vc) {
    int d = threadIdx.x;
    float v = 0.f, c = 0.f;
    for (int k = 0; k < DD; k++) {
        float wv = W0[d * DD + k];
        v += lw[k] * wv;
        c += lb[k] * wv;
    }
    vc[d] = v;
    vc[DD + d] = c;
}

__global__ void k_fill0(const float* __restrict__ wts, const float* __restrict__ vc,
                        float* __restrict__ h) {
    int t = blockIdx.x * blockDim.x + threadIdx.x;
    if (t >= NN * 32) return;
    int n = t >> 5, k4 = t & 31;
    float w = wts[n];
    float4 v = *(const float4*)(vc + k4 * 4);
    float4 c = *(const float4*)(vc + DD + k4 * 4);
    float4 r = make_float4(w * v.x + c.x, w * v.y + c.y, w * v.z + c.z, w * v.w + c.w);
    *(float4*)(h + (size_t)t * 4) = r;
}

// ---------------- W split (plain row-major bf16 hi/lo) ----------------------
__global__ void k_wsplit(const float* __restrict__ fcW, __nv_bfloat16* __restrict__ whi,
                         __nv_bfloat16* __restrict__ wlo) {
    int t = blockIdx.x * blockDim.x + threadIdx.x;
    if (t >= 3 * DD * DD) return;
    float w = fcW[t];
    __nv_bfloat16 hi = __float2bfloat16(w);
    __nv_bfloat16 lo = __float2bfloat16(w - __bfloat162float(hi));
    whi[t] = hi;
    wlo[t] = lo;
}

// ---------------- CSR build ----------------
__global__ void k_deg_init(int* __restrict__ deg, int* __restrict__ fill) {
    int t = blockIdx.x * blockDim.x + threadIdx.x;
    if (t < NN) { deg[t] = 1; fill[t] = 0; }
}

__global__ void k_deg(const int* __restrict__ dst, int* __restrict__ deg) {
    int t = blockIdx.x * blockDim.x + threadIdx.x;
    if (t < EE) atomicAdd(&deg[dst[t]], 1);
}

__global__ void k_scan(const int* __restrict__ deg, int* __restrict__ rowptr) {
    __shared__ int part[1024];
    int t = threadIdx.x;
    const int CH = (NN + 1023) / 1024;
    int start = t * CH;
    int end = start + CH; if (end > NN) end = NN;
    int s = 0;
    for (int i = start; i < end; i++) s += deg[i];
    part[t] = s;
    __syncthreads();
    for (int off = 1; off < 1024; off <<= 1) {
        int v = (t >= off) ? part[t - off] : 0;
        __syncthreads();
        part[t] += v;
        __syncthreads();
    }
    int base = (t == 0) ? 0 : part[t - 1];
    for (int i = start; i < end; i++) { rowptr[i] = base; base += deg[i]; }
    if (t == 1023) rowptr[NN] = part[1023];
}

__global__ void k_csr_fill(const int* __restrict__ src, const int* __restrict__ dst,
                           const int* __restrict__ rowptr, int* __restrict__ fill,
                           int* __restrict__ col) {
    int e = blockIdx.x * blockDim.x + threadIdx.x;
    if (e >= ETOT) return;
    int s_ = (e < EE) ? src[e] : e - EE;
    int d_ = (e < EE) ? dst[e] : e - EE;
    int pos = rowptr[d_] + atomicAdd(&fill[d_], 1);
    col[pos] = s_;
}

// ---------------- tensor-core transform via mma.sync bf16 -------------------
// h = leaky(x) @ W^T.  Split: D = xh*Wh + xh*Wl + xl*Wh (fp32 accum).
// CTA: 128 nodes x 128 outs, 8 warps (4M x 2N), warp tile 32x64.
#define XPITCH 136
#define SM_XH 0
#define SM_XL (128 * XPITCH)
#define SM_WH (2 * 128 * XPITCH)
#define SM_WL (3 * 128 * XPITCH)
#define SMEM_MMA (4 * 128 * XPITCH * 2)

__device__ __forceinline__ void mma16816(float* c, const uint32_t* a, const uint32_t* b) {
    asm volatile(
        "mma.sync.aligned.m16n8k16.row.col.f32.bf16.bf16.f32 "
        "{%0,%1,%2,%3}, {%4,%5,%6,%7}, {%8,%9}, {%0,%1,%2,%3};"
        : "+f"(c[0]), "+f"(c[1]), "+f"(c[2]), "+f"(c[3])
        : "r"(a[0]), "r"(a[1]), "r"(a[2]), "r"(a[3]), "r"(b[0]), "r"(b[1]));
}

__global__ __launch_bounds__(256, 1) void k_transform_mma(const float* __restrict__ x,
                                                          const __nv_bfloat16* __restrict__ Whi,
                                                          const __nv_bfloat16* __restrict__ Wlo,
                                                          float* __restrict__ h) {
    extern __shared__ __nv_bfloat16 sm[];
    __nv_bfloat16* sXh = sm + SM_XH;
    __nv_bfloat16* sXl = sm + SM_XL;
    __nv_bfloat16* sWh = sm + SM_WH;
    __nv_bfloat16* sWl = sm + SM_WL;
    int tid = threadIdx.x;
    int nb = blockIdx.x * 128;

    // load W hi/lo (row-major [128][128] -> padded [128][136])
    {
        const uint4* wh4 = (const uint4*)Whi;
        const uint4* wl4 = (const uint4*)Wlo;
#pragma unroll
        for (int i = 0; i < 8; i++) {
            int idx = tid + i * 256;          // 2048 uint4 = 16384 bf16
            int r = idx >> 4, c = idx & 15;
            *(uint4*)&sWh[r * XPITCH + c * 8] = wh4[idx];
            *(uint4*)&sWl[r * XPITCH + c * 8] = wl4[idx];
        }
    }

    // load x: 2 threads per row, leaky + split hi/lo
    {
        int row = tid >> 1, half = tid & 1;
        int n = nb + row;
        int kb = half * 64;
        if (n < NN) {
            const float4* xr = (const float4*)(x + (size_t)n * DD) + half * 16;
#pragma unroll
            for (int i = 0; i < 16; i++) {
                float4 v = xr[i];
                float f[4] = {v.x, v.y, v.z, v.w};
                uint32_t hw[2], lw[2];
#pragma unroll
                for (int j = 0; j < 4; j += 2) {
                    float a = f[j] >= 0.f ? f[j] : 0.01f * f[j];
                    float b = f[j + 1] >= 0.f ? f[j + 1] : 0.01f * f[j + 1];
                    __nv_bfloat16 ah = __float2bfloat16(a);
                    __nv_bfloat16 bh = __float2bfloat16(b);
                    __nv_bfloat16 al = __float2bfloat16(a - __bfloat162float(ah));
                    __nv_bfloat16 bl = __float2bfloat16(b - __bfloat162float(bh));
                    hw[j >> 1] = (uint32_t)__bfloat16_as_ushort(ah) |
                                 ((uint32_t)__bfloat16_as_ushort(bh) << 16);
                    lw[j >> 1] = (uint32_t)__bfloat16_as_ushort(al) |
                                 ((uint32_t)__bfloat16_as_ushort(bl) << 16);
                }
                *(uint2*)&sXh[row * XPITCH + kb + i * 4] = make_uint2(hw[0], hw[1]);
                *(uint2*)&sXl[row * XPITCH + kb + i * 4] = make_uint2(lw[0], lw[1]);
            }
        } else {
            uint2 z = make_uint2(0u, 0u);
#pragma unroll
            for (int i = 0; i < 16; i++) {
                *(uint2*)&sXh[row * XPITCH + kb + i * 4] = z;
                *(uint2*)&sXl[row * XPITCH + kb + i * 4] = z;
            }
        }
    }
    __syncthreads();

    int wid = tid >> 5, lane = tid & 31;
    int g = lane >> 2, tig = lane & 3;
    int mbase = (wid >> 1) * 32;
    int nbase = (wid & 1) * 64;

    float acc[2][8][4];
#pragma unroll
    for (int mt = 0; mt < 2; mt++)
#pragma unroll
        for (int nt = 0; nt < 8; nt++)
#pragma unroll
            for (int c = 0; c < 4; c++) acc[mt][nt][c] = 0.f;

    const __nv_bfloat16* Ab[3] = {sXh, sXh, sXl};
    const __nv_bfloat16* Bb[3] = {sWh, sWl, sWh};
#pragma unroll
    for (int p = 0; p < 3; p++) {
        const __nv_bfloat16* A = Ab[p];
        const __nv_bfloat16* B = Bb[p];
#pragma unroll
        for (int ks = 0; ks < 8; ks++) {
            int k0 = ks * 16 + tig * 2;
            uint32_t a[2][4], b[8][2];
#pragma unroll
            for (int mt = 0; mt < 2; mt++) {
                int r = mbase + mt * 16 + g;
                a[mt][0] = *(const uint32_t*)&A[r * XPITCH + k0];
                a[mt][1] = *(const uint32_t*)&A[(r + 8) * XPITCH + k0];
                a[mt][2] = *(const uint32_t*)&A[r * XPITCH + k0 + 8];
                a[mt][3] = *(const uint32_t*)&A[(r + 8) * XPITCH + k0 + 8];
            }
#pragma unroll
            for (int nt = 0; nt < 8; nt++) {
                int n = nbase + nt * 8 + g;
                b[nt][0] = *(const uint32_t*)&B[n * XPITCH + k0];
                b[nt][1] = *(const uint32_t*)&B[n * XPITCH + k0 + 8];
            }
#pragma unroll
            for (int mt = 0; mt < 2; mt++)
#pragma unroll
                for (int nt = 0; nt < 8; nt++) mma16816(acc[mt][nt], a[mt], b[nt]);
        }
    }

    // stage C through smem (reuse sXh/sXl region)
    __syncthreads();
    float* stg = (float*)sm;
#pragma unroll
    for (int mt = 0; mt < 2; mt++) {
        int r = mbase + mt * 16 + g;
#pragma unroll
        for (int nt = 0; nt < 8; nt++) {
            int c0 = nbase + nt * 8 + tig * 2;
            stg[r * 132 + c0] = acc[mt][nt][0];
            stg[r * 132 + c0 + 1] = acc[mt][nt][1];
            stg[(r + 8) * 132 + c0] = acc[mt][nt][2];
            stg[(r + 8) * 132 + c0 + 1] = acc[mt][nt][3];
        }
    }
    __syncthreads();

    int col = tid & 127;
#pragma unroll
    for (int r = tid >> 7; r < 128; r += 2) {
        int n2 = nb + r;
        if (n2 < NN) h[(size_t)n2 * DD + col] = stg[r * 132 + col];
    }
}

// ---------------- el/er per node ----------------
__global__ void k_elar(const float* __restrict__ h, const float* __restrict__ al,
                       const float* __restrict__ ar, float* __restrict__ el,
                       float* __restrict__ er) {
    int w = (blockIdx.x * blockDim.x + threadIdx.x) >> 5;
    int lane = threadIdx.x & 31;
    if (w >= NN) return;
    float4 hv = *(const float4*)(h + (size_t)w * DD + lane * 4);
    float4 a4 = *(const float4*)(al + lane * 4);
    float4 b4 = *(const float4*)(ar + lane * 4);
    float pl = hv.x * a4.x + hv.y * a4.y + hv.z * a4.z + hv.w * a4.w;
    float pr = hv.x * b4.x + hv.y * b4.y + hv.z * b4.z + hv.w * b4.w;
    pl += __shfl_down_sync(0xffffffffu, pl, 4);
    pl += __shfl_down_sync(0xffffffffu, pl, 2);
    pl += __shfl_down_sync(0xffffffffu, pl, 1);
    pr += __shfl_down_sync(0xffffffffu, pr, 4);
    pr += __shfl_down_sync(0xffffffffu, pr, 2);
    pr += __shfl_down_sync(0xffffffffu, pr, 1);
    if ((lane & 7) == 0) {
        int hi = w * HH + (lane >> 3);
        el[hi] = pl;
        er[hi] = pr;
    }
}

// ---------------- fused softmax aggregation, MLP-optimized ------------------
// warp per node; phase 1 computes edge scores in PARALLEL across lanes and
// caches them in smem; phase 2 does the h-gather with unrolled (MLP=4) loads.
__device__ __forceinline__ float4 leaky4(float4 v) {
    v.x = v.x >= 0.f ? v.x : 0.2f * v.x;
    v.y = v.y >= 0.f ? v.y : 0.2f * v.y;
    v.z = v.z >= 0.f ? v.z : 0.2f * v.z;
    v.w = v.w >= 0.f ? v.w : 0.2f * v.w;
    return v;
}

#define ECAP 64

__global__ __launch_bounds__(256) void k_agg(const int* __restrict__ rowptr,
                                             const int* __restrict__ col,
                                             const float* __restrict__ el,
                                             const float* __restrict__ er,
                                             const float* __restrict__ h,
                                             const float* __restrict__ cb,
                                             float* __restrict__ out) {
    __shared__ float4 se[8][ECAP];
    int w = (blockIdx.x * blockDim.x + threadIdx.x) >> 5;
    int wid = threadIdx.x >> 5;
    int lane = threadIdx.x & 31;
    if (w >= NN) return;
    int beg = rowptr[w];
    int deg = rowptr[w + 1] - beg;
    float4 erd = *(const float4*)(er + w * HH);

    // phase 1: parallel score computation + smem cache + warp max
    float4 m = make_float4(-CUDART_INF_F, -CUDART_INF_F, -CUDART_INF_F, -CUDART_INF_F);
    for (int c = 0; c < deg; c += 32) {
        int i = c + lane;
        if (i < deg) {
            int s_ = __ldg(&col[beg + i]);
            float4 e4 = *(const float4*)(el + s_ * HH);
            e4 = leaky4(make_float4(e4.x + erd.x, e4.y + erd.y, e4.z + erd.z, e4.w + erd.w));
            if (i < ECAP) se[wid][i] = e4;
            m.x = fmaxf(m.x, e4.x); m.y = fmaxf(m.y, e4.y);
            m.z = fmaxf(m.z, e4.z); m.w = fmaxf(m.w, e4.w);
        }
    }
#pragma unroll
    for (int o = 16; o; o >>= 1) {
        m.x = fmaxf(m.x, __shfl_xor_sync(0xffffffffu, m.x, o));
        m.y = fmaxf(m.y, __shfl_xor_sync(0xffffffffu, m.y, o));
        m.z = fmaxf(m.z, __shfl_xor_sync(0xffffffffu, m.z, o));
        m.w = fmaxf(m.w, __shfl_xor_sync(0xffffffffu, m.w, o));
    }
    __syncwarp();

    // phase 2: lane owns features [lane*4, lane*4+4), head = lane>>3
    int head = lane >> 3;
    float mh = (head == 0) ? m.x : (head == 1) ? m.y : (head == 2) ? m.z : m.w;
    float sum = 0.f;
    float4 acc = make_float4(0.f, 0.f, 0.f, 0.f);
#pragma unroll 4
    for (int i = 0; i < deg; i++) {
        int s_ = __ldg(&col[beg + i]);
        float4 e4;
        if (i < ECAP) {
            e4 = se[wid][i];
        } else {
            e4 = *(const float4*)(el + s_ * HH);
            e4 = leaky4(make_float4(e4.x + erd.x, e4.y + erd.y, e4.z + erd.z, e4.w + erd.w));
        }
        float eh = (head == 0) ? e4.x : (head == 1) ? e4.y : (head == 2) ? e4.z : e4.w;
        float wv = __expf(eh - mh);
        sum += wv;
        float4 hv = *(const float4*)(h + (size_t)s_ * DD + lane * 4);
        acc.x += hv.x * wv; acc.y += hv.y * wv;
        acc.z += hv.z * wv; acc.w += hv.w * wv;
    }
    float inv = 1.f / sum;
    float4 b = *(const float4*)(cb + lane * 4);
    float4 r = make_float4(acc.x * inv + b.x, acc.y * inv + b.y,
                           acc.z * inv + b.z, acc.w * inv + b.w);
    *(float4*)(out + (size_t)w * DD + lane * 4) = r;
}

// ---------------- final prediction head ----------------
__global__ void k_pred(const float* __restrict__ x, const float* __restrict__ pw,
                       const float* __restrict__ pb, float* __restrict__ out) {
    int w = (blockIdx.x * blockDim.x + threadIdx.x) >> 5;
    int lane = threadIdx.x & 31;
    if (w >= NN) return;
    float4 xv = *(const float4*)(x + (size_t)w * DD + lane * 4);
    float4 wv = *(const float4*)(pw + lane * 4);
    float p = xv.x * wv.x + xv.y * wv.y + xv.z * wv.z + xv.w * wv.w;
    p += __shfl_down_sync(0xffffffffu, p, 16);
    p += __shfl_down_sync(0xffffffffu, p, 8);
    p += __shfl_down_sync(0xffffffffu, p, 4);
    p += __shfl_down_sync(0xffffffffu, p, 2);
    p += __shfl_down_sync(0xffffffffu, p, 1);
    if (lane == 0) out[w] = p + pb[0];
}

extern "C" void kernel_launch(void* const* d_in, const int* in_sizes, int n_in,
                              void* d_out, int out_size) {
    const float* weights = (const float*)d_in[0];
    const float* lin_W   = (const float*)d_in[1];
    const float* lin_b   = (const float*)d_in[2];
    const float* fc_W    = (const float*)d_in[3];
    const float* attn_l  = (const float*)d_in[4];
    const float* attn_r  = (const float*)d_in[5];
    const float* conv_b  = (const float*)d_in[6];
    const float* pred_W  = (const float*)d_in[7];
    const float* pred_b  = (const float*)d_in[8];
    const int*   src     = (const int*)d_in[9];
    const int*   dst     = (const int*)d_in[10];

    float *bufA, *bufB, *bufH, *el, *er, *vc;
    int *deg, *fill, *rowptr, *colp;
    __nv_bfloat16 *whi, *wlo;
    cudaGetSymbolAddress((void**)&bufA, d_bufA);
    cudaGetSymbolAddress((void**)&bufB, d_bufB);
    cudaGetSymbolAddress((void**)&bufH, d_bufH);
    cudaGetSymbolAddress((void**)&el, d_el);
    cudaGetSymbolAddress((void**)&er, d_er);
    cudaGetSymbolAddress((void**)&vc, d_vc);
    cudaGetSymbolAddress((void**)&deg, d_deg);
    cudaGetSymbolAddress((void**)&fill, d_fill);
    cudaGetSymbolAddress((void**)&rowptr, d_rowptr);
    cudaGetSymbolAddress((void**)&colp, d_col);
    cudaGetSymbolAddress((void**)&whi, d_whi);
    cudaGetSymbolAddress((void**)&wlo, d_wlo);

    cudaFuncSetAttribute(k_transform_mma, cudaFuncAttributeMaxDynamicSharedMemorySize,
                         SMEM_MMA);

    // CSR build (graph identical for all 3 layers)
    k_deg_init<<<(NN + 255) / 256, 256>>>(deg, fill);
    k_deg<<<(EE + 255) / 256, 256>>>(dst, deg);
    k_scan<<<1, 1024>>>(deg, rowptr);
    k_csr_fill<<<(ETOT + 255) / 256, 256>>>(src, dst, rowptr, fill, colp);

    // W split for layers 1,2 (layer 0 uses rank-1 collapse)
    k_wsplit<<<(3 * DD * DD + 255) / 256, 256>>>(fc_W, whi, wlo);

    // layer 0 transform
    k_rank1<<<1, DD>>>(lin_W, lin_b, fc_W, vc);
    k_fill0<<<(NN * 32 + 255) / 256, 256>>>(weights, vc, bufH);

    const float* xin = nullptr;
    float* xout = bufA;
    for (int l = 0; l < 3; l++) {
        if (l > 0)
            k_transform_mma<<<(NN + 127) / 128, 256, SMEM_MMA>>>(
                xin, whi + l * DD * DD, wlo + l * DD * DD, bufH);
        k_elar<<<(NN + 7) / 8, 256>>>(bufH, attn_l + l * HH * 32, attn_r + l * HH * 32,
                                      el, er);
        k_agg<<<(NN + 7) / 8, 256>>>(rowptr, colp, el, er, bufH, conv_b + l * DD, xout);
        xin = xout;
        xout = (l == 0) ? bufB : bufA;
    }
    k_pred<<<(NN + 7) / 8, 256>>>(xin, pred_W, pred_b, (float*)d_out);
}